// round 2
// baseline (speedup 1.0000x reference)
#include <cuda_runtime.h>
#include <math.h>

#define BB 8
#define WW 20
#define MM 2048
#define HSCD 16
#define HID 32
#define NHH 32
#define DG 80
#define SPCAP 96

// ---------------- scratch (device globals; no allocations) ----------------
__device__ float g_hSC[BB*MM*HSCD];
__device__ float g_kpart[BB*8*1056];
__device__ float g_gram[BB*1024];
__device__ float g_ksum[BB*32];
__device__ float g_rn[BB*MM];
__device__ float g_hT[BB*MM*NHH];
__device__ float g_t[BB*MM];
__device__ float g_cgp[16*BB*MM];
__device__ float g_c[BB*MM];
__device__ float g_tc[BB*MM];
__device__ float g_spv[MM*SPCAP];
__device__ int   g_spi[MM*SPCAP];
__device__ int   g_spc[MM];
__device__ float g_dinv[BB*MM];
__device__ float g_node0[BB*MM*DG];
__device__ float g_node1[BB*MM*DG];
__device__ float g_node2[BB*MM*DG];
__device__ float g_u[BB*DG];

__device__ __forceinline__ float sigf(float x){ return 1.f/(1.f+expf(-x)); }
__device__ __forceinline__ float eluf(float x){ return x>0.f ? x : expf(x)-1.f; }

// ---------------- 1) h_SC = einsum('bwm,wk->bmk', x, Wt) + bt ----------------
__global__ void k_hsc(const float* __restrict__ x, const float* __restrict__ Wt,
                      const float* __restrict__ bt){
    __shared__ float xs[WW*256];
    __shared__ float sWt[WW*HSCD];
    __shared__ float sbt[HSCD];
    int b = blockIdx.x, mt = blockIdx.y, tid = threadIdx.x;
    int m0 = mt*256;
    #pragma unroll
    for (int w = 0; w < WW; ++w) xs[w*256+tid] = x[(b*WW+w)*MM + m0 + tid];
    for (int i = tid; i < WW*HSCD; i += 256) sWt[i] = Wt[i];   // FIX: 320 > 256
    if (tid < HSCD) sbt[tid] = bt[tid];
    __syncthreads();
    float hv[HSCD];
    #pragma unroll
    for (int k = 0; k < HSCD; ++k) hv[k] = sbt[k];
    #pragma unroll
    for (int w = 0; w < WW; ++w){
        float xv = xs[w*256+tid];
        #pragma unroll
        for (int k = 0; k < HSCD; ++k) hv[k] = fmaf(xv, sWt[w*HSCD+k], hv[k]);
    }
    float* op = &g_hSC[(size_t)(b*MM + m0 + tid)*HSCD];
    #pragma unroll
    for (int k = 0; k < HSCD; ++k) op[k] = hv[k];
}

// ---------------- 2) per-batch key sum + Gram (partials) ----------------
__global__ void k_kstats(const float* __restrict__ WKw, const float* __restrict__ WKb){
    __shared__ float sW[HSCD*HID + HID];
    __shared__ float Ks[256*33];
    int b = blockIdx.x, ch = blockIdx.y, tid = threadIdx.x;
    for (int i = tid; i < HSCD*HID + HID; i += 256)
        sW[i] = (i < HSCD*HID) ? WKw[i] : WKb[i - HSCD*HID];
    __syncthreads();
    int m = ch*256 + tid;
    const float* hp = &g_hSC[(size_t)(b*MM+m)*HSCD];
    float hc[HSCD];
    #pragma unroll
    for (int c = 0; c < HSCD; ++c) hc[c] = hp[c];
    #pragma unroll
    for (int h = 0; h < HID; ++h){
        float a = sW[HSCD*HID + h];
        #pragma unroll
        for (int c = 0; c < HSCD; ++c) a = fmaf(hc[c], sW[c*HID+h], a);
        Ks[tid*33 + h] = a;
    }
    __syncthreads();
    float* outp = &g_kpart[(size_t)(b*8 + ch)*1056];
    #pragma unroll
    for (int e = 0; e < 4; ++e){
        int idx = tid*4 + e, i = idx >> 5, j = idx & 31;
        float s = 0.f;
        for (int r = 0; r < 256; ++r) s = fmaf(Ks[r*33+i], Ks[r*33+j], s);
        outp[idx] = s;
    }
    if (tid < 32){
        float s = 0.f;
        for (int r = 0; r < 256; ++r) s += Ks[r*33+tid];
        outp[1024+tid] = s;
    }
}

__global__ void k_kreduce(){
    int b = blockIdx.x, tid = threadIdx.x;
    for (int idx = tid; idx < 1056; idx += 256){
        float s = 0.f;
        #pragma unroll
        for (int c = 0; c < 8; ++c) s += g_kpart[(size_t)(b*8+c)*1056 + idx];
        if (idx < 1024) g_gram[b*1024+idx] = s;
        else            g_ksum[b*32 + idx - 1024] = s;
    }
}

// ---------------- 3) normalized attention row sums ----------------
__global__ void k_rownorm(const float* __restrict__ WQw, const float* __restrict__ WQb){
    __shared__ float sW[HSCD*HID];
    __shared__ float sb[HID];
    __shared__ float sG[1024];
    __shared__ float sk[32];
    int b = blockIdx.x, tid = threadIdx.x;
    for (int i = tid; i < HSCD*HID; i += 256) sW[i] = WQw[i];
    if (tid < HID) sb[tid] = WQb[tid];
    for (int i = tid; i < 1024; i += 256) sG[i] = g_gram[b*1024+i];
    if (tid < 32) sk[tid] = g_ksum[b*32+tid];
    __syncthreads();
    int m = blockIdx.y*256 + tid;
    const float* hp = &g_hSC[(size_t)(b*MM+m)*HSCD];
    float hc[HSCD];
    #pragma unroll
    for (int c = 0; c < HSCD; ++c) hc[c] = hp[c];
    float q[HID];
    #pragma unroll
    for (int h = 0; h < HID; ++h){
        float a = sb[h];
        #pragma unroll
        for (int c = 0; c < HSCD; ++c) a = fmaf(hc[c], sW[c*HID+h], a);
        q[h] = a;
    }
    float num = 0.f, den = 0.f;
    #pragma unroll
    for (int h = 0; h < HID; ++h) num = fmaf(q[h], sk[h], num);
    #pragma unroll
    for (int i = 0; i < HID; ++i){
        float tmp = 0.f;
        #pragma unroll
        for (int j = 0; j < HID; ++j) tmp = fmaf(sG[i*32+j], q[j], tmp);
        den = fmaf(q[i], tmp, den);
    }
    g_rn[b*MM+m] = num / fmaxf(sqrtf(fmaxf(den, 0.f)), 1e-12f);
}

// ---------------- 4) GRU: warp per sequence ----------------
__global__ void k_gru(const float* __restrict__ x, const float* __restrict__ wih,
                      const float* __restrict__ whh, const float* __restrict__ bih,
                      const float* __restrict__ bhh){
    __shared__ float4 sW[1024];   // sW[j*32+l] = {whh[l][j], whh[32+l][j], whh[64+l][j], 0}
    int tid = threadIdx.x, lane = tid & 31, wid = tid >> 5;
    for (int idx = tid; idx < 1024; idx += 256){
        int j = idx >> 5, l = idx & 31;
        sW[idx] = make_float4(whh[l*32+j], whh[(l+32)*32+j], whh[(l+64)*32+j], 0.f);
    }
    __syncthreads();
    int seq = blockIdx.x*8 + wid;
    int b = seq >> 11, m = seq & 2047;
    float wr = wih[lane], wz = wih[32+lane], wn = wih[64+lane];
    float br = bih[lane], bz = bih[32+lane], bn = bih[64+lane];
    float hr = bhh[lane], hz = bhh[32+lane], hn = bhh[64+lane];
    float h = 0.f;
    for (int t = 0; t < WW; ++t){
        float xt = x[(b*WW+t)*MM + m];
        float ar = hr, az = hz, an = hn;
        #pragma unroll
        for (int j = 0; j < 32; ++j){
            float hj = __shfl_sync(0xffffffffu, h, j);
            float4 w = sW[j*32 + lane];
            ar = fmaf(w.x, hj, ar); az = fmaf(w.y, hj, az); an = fmaf(w.z, hj, an);
        }
        float r = sigf(fmaf(xt, wr, br) + ar);
        float z = sigf(fmaf(xt, wz, bz) + az);
        float n = tanhf(fmaf(xt, wn, bn) + r*an);
        h = (1.f - z)*n + z*h;
    }
    g_hT[(size_t)seq*32 + lane] = h;
}

// ---------------- 5) score s -> t (column-constant normalized a_mx) ----------------
__global__ void k_score(const float* __restrict__ W1, const float* __restrict__ W2,
                        const float* __restrict__ b1, const float* __restrict__ V,
                        const float* __restrict__ bv){
    __shared__ float sW[16*32];
    __shared__ float sb[16];
    __shared__ float sV[16];
    int tid = threadIdx.x;
    for (int i = tid; i < 512; i += 256) sW[i] = W1[i] + W2[i];
    if (tid < 16){ sb[tid] = b1[tid]; sV[tid] = V[tid]; }
    __syncthreads();
    int gid = blockIdx.x*256 + tid;
    const float* hp = &g_hT[(size_t)gid*32];
    float ht[32];
    #pragma unroll
    for (int h = 0; h < 32; ++h) ht[h] = hp[h];
    float s = bv[0];
    #pragma unroll
    for (int o = 0; o < 16; ++o){
        float a = sb[o];
        #pragma unroll
        for (int h = 0; h < 32; ++h) a = fmaf(ht[h], sW[o*32+h], a);
        s = fmaf(eluf(a), sV[o], s);
    }
    g_t[gid] = s / fmaxf(fabsf(s)*45.254833995939045f, 1e-12f);
}

// ---------------- 6) c_gate column vector: cg[b,j] = sigma(t[b,:]·Wb[:,j] + wb) ----------------
__global__ void k_cg_part(const float* __restrict__ Wb){
    __shared__ float ts[8*128];
    int jt = blockIdx.x, nc = blockIdx.y, tid = threadIdx.x;
    int n0 = nc*128;
    for (int idx = tid; idx < 1024; idx += 256){
        int bb = idx >> 7, nn = idx & 127;
        ts[idx] = g_t[bb*MM + n0 + nn];
    }
    __syncthreads();
    int j = jt*256 + tid;
    float acc[8] = {0,0,0,0,0,0,0,0};
    for (int nn = 0; nn < 128; ++nn){
        float w = Wb[(size_t)(n0+nn)*MM + j];
        #pragma unroll
        for (int bb = 0; bb < 8; ++bb) acc[bb] = fmaf(ts[bb*128+nn], w, acc[bb]);
    }
    #pragma unroll
    for (int bb = 0; bb < 8; ++bb) g_cgp[(size_t)(nc*8+bb)*MM + j] = acc[bb];
}

__global__ void k_cg_fin(const float* __restrict__ wb){
    int gid = blockIdx.x*256 + threadIdx.x;
    int b = gid >> 11, j = gid & 2047;
    float s = wb[0];
    #pragma unroll
    for (int nc = 0; nc < 16; ++nc) s += g_cgp[(size_t)(nc*8+b)*MM + j];
    float c = sigf(s);
    g_c[gid] = c;
    g_tc[gid] = g_t[gid]*(1.f - c);
}

// ---------------- 7) sparse spatial = sigmoid(d_gate*deg_i*deg_j)*adj_orig ----------------
__global__ void k_spatial(const float* __restrict__ d_gate, const float* __restrict__ adj_orig,
                          const float* __restrict__ degree){
    int tid = threadIdx.x, lane = tid & 31, wid = tid >> 5;
    int i = blockIdx.x*8 + wid;
    float di = degree[i];
    int cnt = 0;
    for (int j0 = 0; j0 < MM; j0 += 32){
        int j = j0 + lane;
        float a = adj_orig[(size_t)i*MM + j];
        bool nz = a > 0.f;
        unsigned mask = __ballot_sync(0xffffffffu, nz);
        if (nz){
            float v = a * sigf(d_gate[(size_t)i*MM + j]*di*degree[j]);
            int pos = cnt + __popc(mask & ((1u << lane) - 1u));
            if (pos < SPCAP){ g_spi[i*SPCAP+pos] = j; g_spv[i*SPCAP+pos] = v; }
        }
        cnt += __popc(mask);
    }
    if (lane == 0) g_spc[i] = min(cnt, SPCAP);
}

// ---------------- 8) degree counts of adj_fin > 0 ----------------
__global__ void k_deg(const float* __restrict__ adj_geo){
    __shared__ float cs[8*512];
    __shared__ float tcs[8*512];
    __shared__ int sdeg[8];
    int i = blockIdx.x, tid = threadIdx.x;
    if (tid < 8) sdeg[tid] = 0;
    int cnt[8] = {0,0,0,0,0,0,0,0};
    for (int j0 = 0; j0 < MM; j0 += 512){
        __syncthreads();
        for (int idx = tid; idx < 4096; idx += 256){
            int bb = idx >> 9, jj = idx & 511;
            cs[idx]  = g_c[bb*MM + j0 + jj];
            tcs[idx] = g_tc[bb*MM + j0 + jj];
        }
        __syncthreads();
        for (int j = tid; j < 512; j += 256){
            float ag = adj_geo[(size_t)i*MM + j0 + j];
            #pragma unroll
            for (int bb = 0; bb < 8; ++bb){
                float dyn = fmaf(ag, cs[bb*512+j], tcs[bb*512+j]);
                cnt[bb] += (dyn > 0.f);
            }
        }
    }
    #pragma unroll
    for (int bb = 0; bb < 8; ++bb){
        int v = cnt[bb];
        #pragma unroll
        for (int o = 16; o; o >>= 1) v += __shfl_down_sync(0xffffffffu, v, o);
        if ((tid & 31) == 0) atomicAdd(&sdeg[bb], v);
    }
    __syncthreads();
    int sc = g_spc[i];
    for (int s = tid; s < sc; s += 256){
        int j = g_spi[i*SPCAP+s]; float v = g_spv[i*SPCAP+s];
        #pragma unroll
        for (int bb = 0; bb < 8; ++bb){
            float dyn = fmaf(adj_geo[(size_t)i*MM + j], g_c[bb*MM+j], g_tc[bb*MM+j]);
            if (dyn <= 0.f && dyn + v > 0.f) atomicAdd(&sdeg[bb], 1);
        }
    }
    __syncthreads();
    if (tid < 8){
        int d = sdeg[tid];
        g_dinv[tid*MM + i] = (d > 0) ? 1.f/(float)d : 0.f;
    }
}

// ---------------- 9) node0 = [h_SC | h_L | h_G] ----------------
__global__ void k_node0(const float* __restrict__ tenc_w, const float* __restrict__ tenc_b,
                        const float* __restrict__ senc_w, const float* __restrict__ senc_b,
                        const float* __restrict__ degree){
    int gid = blockIdx.x*256 + threadIdx.x;
    int m = gid & 2047;
    float* np = &g_node0[(size_t)gid*DG];
    const float* hp = &g_hSC[(size_t)gid*HSCD];
    #pragma unroll
    for (int c = 0; c < HSCD; ++c) np[c] = hp[c];
    float dm = degree[m], rn = g_rn[gid];
    #pragma unroll
    for (int h = 0; h < 32; ++h) np[16+h] = fmaf(dm, senc_w[h], senc_b[h]);
    #pragma unroll
    for (int h = 0; h < 32; ++h) np[48+h] = fmaf(rn, tenc_w[h], tenc_b[h]);
}

// ---------------- 10) rank-1 term u[b,d] = sum_j tc[b,j]*node[b,j,d] ----------------
__global__ void k_u(const float* __restrict__ node){
    __shared__ float red[256];
    int b = blockIdx.x, d = blockIdx.y, tid = threadIdx.x;
    float a = 0.f;
    for (int j = tid; j < MM; j += 256)
        a = fmaf(g_tc[b*MM+j], node[(size_t)(b*MM+j)*DG + d], a);
    red[tid] = a; __syncthreads();
    for (int s = 128; s; s >>= 1){ if (tid < s) red[tid] += red[tid+s]; __syncthreads(); }
    if (tid == 0) g_u[b*DG + d] = red[0];
}

// ---------------- 11) fused GNN layer: node_out = elu(deginv*(geo@(c*node)+sp@node+u) @ gw + gb)
__global__ void k_gemm(const float* __restrict__ nodeIn, float* __restrict__ nodeOut,
                       const float* __restrict__ adj_geo, const float* __restrict__ gw,
                       const float* __restrict__ gb){
    extern __shared__ float sm[];
    float* sG = sm;                  // 80*84
    float* sA = sm + 80*84;          // 128*68
    float* sN = sA + 128*68;         // 64*84
    float* sY = sA;                  // alias after main loop
    int tid = threadIdx.x, q = tid & 3, ig = tid >> 2;
    int i0 = blockIdx.x*128, b = blockIdx.y;
    for (int idx = tid; idx < 6400; idx += 256){
        int d = idx/80, e = idx%80;
        sG[d*84+e] = gw[idx];
    }
    float acc[2][20];
    #pragma unroll
    for (int r = 0; r < 2; ++r)
        #pragma unroll
        for (int k = 0; k < 20; ++k) acc[r][k] = 0.f;

    for (int jt = 0; jt < 32; ++jt){
        int j0 = jt*64;
        __syncthreads();
        for (int v = tid; v < 2048; v += 256){
            int r = v >> 4, c4 = (v & 15) << 2;
            float4 a4 = *(const float4*)&adj_geo[(size_t)(i0+r)*MM + j0 + c4];
            *(float4*)&sA[r*68 + c4] = a4;
        }
        for (int v = tid; v < 1280; v += 256){
            int j = v/20, dd = (v%20) << 2;
            float cj = g_c[b*MM + j0 + j];
            float4 n4 = *(const float4*)&nodeIn[(size_t)(b*MM + j0 + j)*DG + dd];
            n4.x *= cj; n4.y *= cj; n4.z *= cj; n4.w *= cj;
            *(float4*)&sN[j*84 + dd] = n4;
        }
        __syncthreads();
        #pragma unroll 4
        for (int j = 0; j < 64; ++j){
            float a0 = sA[ig*68 + j];
            float a1 = sA[(ig+64)*68 + j];
            const float4* np = (const float4*)&sN[j*84 + q*20];
            #pragma unroll
            for (int v = 0; v < 5; ++v){
                float4 n = np[v];
                acc[0][v*4+0] = fmaf(a0, n.x, acc[0][v*4+0]);
                acc[0][v*4+1] = fmaf(a0, n.y, acc[0][v*4+1]);
                acc[0][v*4+2] = fmaf(a0, n.z, acc[0][v*4+2]);
                acc[0][v*4+3] = fmaf(a0, n.w, acc[0][v*4+3]);
                acc[1][v*4+0] = fmaf(a1, n.x, acc[1][v*4+0]);
                acc[1][v*4+1] = fmaf(a1, n.y, acc[1][v*4+1]);
                acc[1][v*4+2] = fmaf(a1, n.z, acc[1][v*4+2]);
                acc[1][v*4+3] = fmaf(a1, n.w, acc[1][v*4+3]);
            }
        }
    }
    __syncthreads();
    // sparse + rank-1 + deg scaling; stash y rows in shared
    #pragma unroll
    for (int r = 0; r < 2; ++r){
        int i = i0 + ig + r*64;
        int sc = g_spc[i];
        for (int s = 0; s < sc; ++s){
            int j = g_spi[i*SPCAP+s]; float v = g_spv[i*SPCAP+s];
            const float4* np = (const float4*)&nodeIn[(size_t)(b*MM + j)*DG + q*20];
            #pragma unroll
            for (int vv = 0; vv < 5; ++vv){
                float4 n = np[vv];
                acc[r][vv*4+0] = fmaf(v, n.x, acc[r][vv*4+0]);
                acc[r][vv*4+1] = fmaf(v, n.y, acc[r][vv*4+1]);
                acc[r][vv*4+2] = fmaf(v, n.z, acc[r][vv*4+2]);
                acc[r][vv*4+3] = fmaf(v, n.w, acc[r][vv*4+3]);
            }
        }
        float dinv = g_dinv[b*MM + i];
        const float4* up = (const float4*)&g_u[b*DG + q*20];
        #pragma unroll
        for (int vv = 0; vv < 5; ++vv){
            float4 u4 = up[vv];
            float4 y;
            y.x = dinv*(acc[r][vv*4+0] + u4.x);
            y.y = dinv*(acc[r][vv*4+1] + u4.y);
            y.z = dinv*(acc[r][vv*4+2] + u4.z);
            y.w = dinv*(acc[r][vv*4+3] + u4.w);
            *(float4*)&sY[(ig + r*64)*84 + q*20 + vv*4] = y;
        }
    }
    __syncthreads();
    // z = y @ gw + gb, elu
    #pragma unroll
    for (int r = 0; r < 2; ++r){
        int i = i0 + ig + r*64;
        float z[20];
        #pragma unroll
        for (int e = 0; e < 20; ++e) z[e] = gb[q*20+e];
        for (int d = 0; d < 80; ++d){
            float yv = sY[(ig + r*64)*84 + d];
            const float4* gp = (const float4*)&sG[d*84 + q*20];
            #pragma unroll
            for (int v = 0; v < 5; ++v){
                float4 g4 = gp[v];
                z[v*4+0] = fmaf(yv, g4.x, z[v*4+0]);
                z[v*4+1] = fmaf(yv, g4.y, z[v*4+1]);
                z[v*4+2] = fmaf(yv, g4.z, z[v*4+2]);
                z[v*4+3] = fmaf(yv, g4.w, z[v*4+3]);
            }
        }
        float* op = &nodeOut[(size_t)(b*MM + i)*DG + q*20];
        #pragma unroll
        for (int e = 0; e < 20; ++e) op[e] = eluf(z[e]);
    }
}

// ---------------- 12) final projection ----------------
__global__ void k_final(const float* __restrict__ out_w, const float* __restrict__ out_b,
                        float* __restrict__ out){
    __shared__ float sw[272];
    int tid = threadIdx.x;
    for (int i = tid; i < 272; i += 256) sw[i] = out_w[i];
    __syncthreads();
    int gid = blockIdx.x*256 + tid;
    float a = out_b[0];
    const float* n0 = &g_node0[(size_t)gid*DG];
    const float* n1 = &g_node1[(size_t)gid*DG];
    const float* n2 = &g_node2[(size_t)gid*DG];
    const float* ht = &g_hT[(size_t)gid*32];
    #pragma unroll
    for (int d = 0; d < DG; ++d) a = fmaf(n0[d], sw[d], a);
    #pragma unroll
    for (int d = 0; d < DG; ++d) a = fmaf(n1[d], sw[80+d], a);
    #pragma unroll
    for (int d = 0; d < DG; ++d) a = fmaf(n2[d], sw[160+d], a);
    #pragma unroll
    for (int h = 0; h < 32; ++h) a = fmaf(ht[h], sw[240+h], a);
    out[gid] = a;
}

// ---------------- launch ----------------
extern "C" void kernel_launch(void* const* d_in, const int* in_sizes, int n_in,
                              void* d_out, int out_size){
    const float* x       = (const float*)d_in[0];
    const float* Wt      = (const float*)d_in[1];
    const float* bt      = (const float*)d_in[2];
    const float* WQ_w    = (const float*)d_in[3];
    const float* WQ_b    = (const float*)d_in[4];
    const float* WK_w    = (const float*)d_in[5];
    const float* WK_b    = (const float*)d_in[6];
    const float* tenc_w  = (const float*)d_in[7];
    const float* tenc_b  = (const float*)d_in[8];
    const float* senc_w  = (const float*)d_in[9];
    const float* senc_b  = (const float*)d_in[10];
    const float* gru_wih = (const float*)d_in[11];
    const float* gru_whh = (const float*)d_in[12];
    const float* gru_bih = (const float*)d_in[13];
    const float* gru_bhh = (const float*)d_in[14];
    const float* V       = (const float*)d_in[15];
    const float* bv      = (const float*)d_in[16];
    const float* W1      = (const float*)d_in[17];
    const float* b1      = (const float*)d_in[18];
    const float* W2      = (const float*)d_in[19];
    const float* Wb      = (const float*)d_in[20];
    const float* wb      = (const float*)d_in[21];
    const float* d_gate  = (const float*)d_in[22];
    const float* adj_geo = (const float*)d_in[23];
    const float* adj_orig= (const float*)d_in[24];
    const float* degree  = (const float*)d_in[25];
    const float* gnn_w   = (const float*)d_in[26];
    const float* gnn_b   = (const float*)d_in[27];
    const float* out_w   = (const float*)d_in[28];
    const float* out_b   = (const float*)d_in[29];
    float* out = (float*)d_out;

    const int GEMM_SMEM = (80*84 + 128*68 + 64*84) * 4;
    cudaFuncSetAttribute(k_gemm, cudaFuncAttributeMaxDynamicSharedMemorySize, GEMM_SMEM);

    float *n0, *n1, *n2;
    cudaGetSymbolAddress((void**)&n0, g_node0);
    cudaGetSymbolAddress((void**)&n1, g_node1);
    cudaGetSymbolAddress((void**)&n2, g_node2);

    k_hsc<<<dim3(BB, MM/256), 256>>>(x, Wt, bt);
    k_kstats<<<dim3(BB, 8), 256>>>(WK_w, WK_b);
    k_kreduce<<<BB, 256>>>();
    k_rownorm<<<dim3(BB, MM/256), 256>>>(WQ_w, WQ_b);
    k_gru<<<BB*MM/8, 256>>>(x, gru_wih, gru_whh, gru_bih, gru_bhh);
    k_score<<<BB*MM/256, 256>>>(W1, W2, b1, V, bv);
    k_cg_part<<<dim3(8, 16), 256>>>(Wb);
    k_cg_fin<<<BB*MM/256, 256>>>(wb);
    k_spatial<<<MM/8, 256>>>(d_gate, adj_orig, degree);
    k_deg<<<MM, 256>>>(adj_geo);
    k_node0<<<BB*MM/256, 256>>>(tenc_w, tenc_b, senc_w, senc_b, degree);

    k_u<<<dim3(BB, DG), 256>>>(n0);
    k_gemm<<<dim3(16, BB), 256, GEMM_SMEM>>>(n0, n1, adj_geo, gnn_w,        gnn_b);
    k_u<<<dim3(BB, DG), 256>>>(n1);
    k_gemm<<<dim3(16, BB), 256, GEMM_SMEM>>>(n1, n2, adj_geo, gnn_w + 6400, gnn_b + 80);

    k_final<<<BB*MM/256, 256>>>(out_w, out_b, out);
}